// round 14
// baseline (speedup 1.0000x reference)
#include <cuda_runtime.h>
#include <cuda_bf16.h>
#include <math.h>
#include <stdint.h>

#define N_NODES 100000
#define N_EDGES 1600000
#define CH 128
#define OUTC 64
#define NG 64
#define NSCAN_BLOCKS 196   // ceil(100000/512)

// ---------------- scratch (static device globals; no allocation) ----------------
__device__ __align__(16) uint32_t g_msg[N_NODES * 64];  // messages dinv*(h+b), bf16x2
__device__ __align__(16) uint32_t g_act[N_NODES * 64];  // relu'd activations, bf16x2
__device__ float g_dinv[N_NODES];
__device__ int   g_counts[N_NODES];
__device__ int   g_rowstart[N_NODES + 1];
__device__ int   g_rank[N_EDGES];
__device__ int   g_col[N_EDGES];
__device__ int   g_perm[N_NODES];
__device__ unsigned long long g_part[256];   // lookback: flag(bit62) | aggregate
__device__ int   g_ticket;
__device__ int   g_dhist[64];
__device__ int   g_dbase[64];
__device__ int   g_dfill[64];
__device__ __align__(16) __nv_bfloat16 g_wh[3 * CH * CH];  // W^T hi, [layer][n][k]
__device__ __align__(16) __nv_bfloat16 g_wl[3 * CH * CH];  // W^T lo
__device__ __align__(16) float g_pool[NG * CH];
__device__ float g_cnt[NG];

__device__ __forceinline__ float bflo(uint32_t u) {
    return __bfloat162float(__ushort_as_bfloat16((unsigned short)(u & 0xFFFF)));
}
__device__ __forceinline__ float bfhi(uint32_t u) {
    return __bfloat162float(__ushort_as_bfloat16((unsigned short)(u >> 16)));
}
__device__ __forceinline__ uint32_t pack_bf2(float a, float b) {
    __nv_bfloat16 x = __float2bfloat16(a), y = __float2bfloat16(b);
    return (uint32_t)__bfloat16_as_ushort(x) | ((uint32_t)__bfloat16_as_ushort(y) << 16);
}
__device__ __forceinline__ uint4 ldcg_u4(const uint4* p) {
    uint4 v;
    asm volatile("ld.global.cg.v4.u32 {%0,%1,%2,%3}, [%4];"
                 : "=r"(v.x), "=r"(v.y), "=r"(v.z), "=r"(v.w) : "l"(p));
    return v;
}

// ---------------- zero per-call state ----------------
__global__ void k_zero() {
    int i = blockIdx.x * blockDim.x + threadIdx.x;
    if (i < N_NODES) g_counts[i] = 0;
    if (i < NG * CH) g_pool[i] = 0.f;
    if (i < NG)      g_cnt[i] = 0.f;
    if (i < 256)     g_part[i] = 0ULL;
    if (i < 64)      { g_dhist[i] = 0; g_dfill[i] = 0; }
    if (i == 0)      g_ticket = 0;
}

// ---------------- degree histogram + per-edge rank (atomic return value) ----------------
__global__ void k_count(const int* __restrict__ ei) {
    int e4 = blockIdx.x * blockDim.x + threadIdx.x;
    if (e4 < N_EDGES / 4) {
        int4 d = *(const int4*)(ei + N_EDGES + e4 * 4);
        int4 r;
        r.x = atomicAdd(&g_counts[d.x], 1);
        r.y = atomicAdd(&g_counts[d.y], 1);
        r.z = atomicAdd(&g_counts[d.z], 1);
        r.w = atomicAdd(&g_counts[d.w], 1);
        *(int4*)(g_rank + e4 * 4) = r;
    }
}

// ---------------- dinv ----------------
__global__ void k_dinv() {
    int i = blockIdx.x * blockDim.x + threadIdx.x;
    if (i < N_NODES) g_dinv[i] = rsqrtf((float)g_counts[i] + 1.0f);
}

// ---------------- single-pass decoupled-lookback exclusive scan ----------------
__global__ __launch_bounds__(512) void k_scanlb() {
    __shared__ int sh[512];
    __shared__ int s_bid;
    __shared__ int s_prev;
    if (threadIdx.x == 0) s_bid = atomicAdd(&g_ticket, 1);   // ticket = forward progress
    __syncthreads();
    int b = s_bid;
    int t = threadIdx.x;
    int i = b * 512 + t;

    int v = (i < N_NODES) ? g_counts[i] : 0;
    sh[t] = v;
    __syncthreads();
    #pragma unroll
    for (int d = 1; d < 512; d <<= 1) {
        int tv = (t >= d) ? sh[t - d] : 0;
        __syncthreads();
        sh[t] += tv;
        __syncthreads();
    }
    int incl = sh[t];
    int total = sh[511];

    // publish aggregate (single 64-bit packet: flag bit62 | value)
    if (t == 0) {
        unsigned long long pkt = (1ULL << 62) | (unsigned long long)(unsigned)total;
        atomicExch(&g_part[b], pkt);
    }
    // warp 0: sum aggregates of all earlier blocks
    if (t < 32) {
        int prev = 0;
        for (int base = 0; base < b; base += 32) {
            int j = base + t;
            int val = 0;
            if (j < b) {
                unsigned long long p;
                do { p = atomicAdd(&g_part[j], 0ULL); } while (!(p >> 62));
                val = (int)(p & 0xFFFFFFFFULL);
            }
            #pragma unroll
            for (int o = 16; o; o >>= 1) val += __shfl_down_sync(0xFFFFFFFFu, val, o);
            if (t == 0) prev += val;
        }
        if (t == 0) s_prev = prev;
    }
    __syncthreads();
    int prev = s_prev;
    if (i < N_NODES) g_rowstart[i] = prev + incl - v;   // exclusive
    if (i == 0) g_rowstart[N_NODES] = N_EDGES;
}

// ---------------- CSR fill by rank (no atomics) ----------------
__global__ void k_fill(const int* __restrict__ ei) {
    int e4 = blockIdx.x * blockDim.x + threadIdx.x;
    if (e4 < N_EDGES / 4) {
        int4 s = *(const int4*)(ei + e4 * 4);
        int4 d = *(const int4*)(ei + N_EDGES + e4 * 4);
        int4 r = *(const int4*)(g_rank + e4 * 4);
        g_col[g_rowstart[d.x] + r.x] = s.x;
        g_col[g_rowstart[d.y] + r.y] = s.y;
        g_col[g_rowstart[d.z] + r.z] = s.z;
        g_col[g_rowstart[d.w] + r.w] = s.w;
    }
}

// ---------------- degree-sort permutation (counting sort, 64 bins) ----------------
__global__ void k_dhist() {
    int i = blockIdx.x * blockDim.x + threadIdx.x;
    if (i < N_NODES) atomicAdd(&g_dhist[min(g_counts[i], 63)], 1);
}
__global__ void k_dscan() {
    if (threadIdx.x == 0) {
        int acc = 0;
        for (int b = 0; b < 64; b++) { g_dbase[b] = acc; acc += g_dhist[b]; }
    }
}
__global__ void k_perm() {
    int i = blockIdx.x * blockDim.x + threadIdx.x;
    if (i < N_NODES) {
        int b = min(g_counts[i], 63);
        int pos = g_dbase[b] + atomicAdd(&g_dfill[b], 1);
        g_perm[pos] = i;
    }
}

// ---------------- weight convert, all 3 layers ----------------
__global__ void k_wconv3(const float* __restrict__ W1, const float* __restrict__ W2,
                         const float* __restrict__ W3) {
    int i = blockIdx.x * blockDim.x + threadIdx.x;   // i = l*16384 + n*128 + k
    if (i < 3 * CH * CH) {
        int l = i >> 14;
        int n = (i >> 7) & 127, k = i & 127;
        const float* W = (l == 0) ? W1 : (l == 1) ? W2 : W3;
        float w = W[k * CH + n];
        __nv_bfloat16 h = __float2bfloat16(w);
        __nv_bfloat16 lo = __float2bfloat16(w - __bfloat162float(h));
        g_wh[i] = h;
        g_wl[i] = lo;
    }
}

// ---------------- shared GEMM machinery ----------------
#define SM_A  0
#define SM_BH (64 * 272)
#define SM_BL (SM_BH + 128 * 272)
#define SM_TOTAL (SM_BL + 128 * 272)   // 87040 B

__device__ __forceinline__ void mma16816(float* c, const uint32_t* a, const uint32_t* b) {
    asm volatile("mma.sync.aligned.m16n8k16.row.col.f32.bf16.bf16.f32 "
                 "{%0,%1,%2,%3}, {%4,%5,%6,%7}, {%8,%9}, {%0,%1,%2,%3};"
                 : "+f"(c[0]), "+f"(c[1]), "+f"(c[2]), "+f"(c[3])
                 : "r"(a[0]), "r"(a[1]), "r"(a[2]), "r"(a[3]), "r"(b[0]), "r"(b[1]));
}

__device__ __forceinline__ void load_w_smem(char* smem, int layer, int tid) {
    const __nv_bfloat16* wh = g_wh + layer * CH * CH;
    const __nv_bfloat16* wl = g_wl + layer * CH * CH;
    for (int p = tid; p < 128 * 16; p += 256) {
        int n = p >> 4;
        int k8 = (p & 15) * 8;
        uint4 vh = *(const uint4*)(wh + n * CH + k8);
        uint4 vl = *(const uint4*)(wl + n * CH + k8);
        *(uint4*)(smem + SM_BH + n * 272 + k8 * 2) = vh;
        *(uint4*)(smem + SM_BL + n * 272 + k8 * 2) = vl;
    }
}

__device__ __forceinline__ void mma_phase(char* smem, int m0, const float* __restrict__ B,
                                          uint32_t* __restrict__ O, int wid, int lane) {
    int m_w = (wid & 1) * 32;
    int n_w = (wid >> 1) * 32;
    float acc[2][4][4];
    #pragma unroll
    for (int mt = 0; mt < 2; mt++)
        #pragma unroll
        for (int nt = 0; nt < 4; nt++)
            #pragma unroll
            for (int j = 0; j < 4; j++) acc[mt][nt][j] = 0.f;

    int q = lane >> 2;
    int km = (lane & 3) * 2;

    #pragma unroll
    for (int ks = 0; ks < 8; ks++) {
        int k0 = ks * 16;
        uint32_t ah[2][4], bh[4][2], bl[4][2];
        #pragma unroll
        for (int mt = 0; mt < 2; mt++) {
            int r = m_w + mt * 16 + q;
            const char* pa = smem + SM_A + r * 272 + (k0 + km) * 2;
            ah[mt][0] = *(const uint32_t*)(pa);
            ah[mt][1] = *(const uint32_t*)(pa + 8 * 272);
            ah[mt][2] = *(const uint32_t*)(pa + 16);
            ah[mt][3] = *(const uint32_t*)(pa + 8 * 272 + 16);
        }
        #pragma unroll
        for (int nt = 0; nt < 4; nt++) {
            int n = n_w + nt * 8 + q;
            const char* pb = smem + n * 272 + (k0 + km) * 2;
            bh[nt][0] = *(const uint32_t*)(pb + SM_BH);
            bh[nt][1] = *(const uint32_t*)(pb + SM_BH + 16);
            bl[nt][0] = *(const uint32_t*)(pb + SM_BL);
            bl[nt][1] = *(const uint32_t*)(pb + SM_BL + 16);
        }
        #pragma unroll
        for (int mt = 0; mt < 2; mt++)
            #pragma unroll
            for (int nt = 0; nt < 4; nt++) {
                mma16816(acc[mt][nt], ah[mt], bh[nt]);
                mma16816(acc[mt][nt], ah[mt], bl[nt]);
            }
    }

    #pragma unroll
    for (int nt = 0; nt < 4; nt++) {
        int c = n_w + nt * 8 + km;
        float bx = __ldg(B + c), by = __ldg(B + c + 1);
        #pragma unroll
        for (int mt = 0; mt < 2; mt++) {
            int r0 = m0 + m_w + mt * 16 + q;
            if (r0 < N_NODES) {
                float dr = g_dinv[r0];
                O[(size_t)r0 * 64 + (c >> 1)] =
                    pack_bf2(dr * (acc[mt][nt][0] + bx), dr * (acc[mt][nt][1] + by));
            }
            int r1 = r0 + 8;
            if (r1 < N_NODES) {
                float dr = g_dinv[r1];
                O[(size_t)r1 * 64 + (c >> 1)] =
                    pack_bf2(dr * (acc[mt][nt][2] + bx), dr * (acc[mt][nt][3] + by));
            }
        }
    }
}

// ---------------- layer 1 GEMM: fp32 input -> bf16 A ----------------
__global__ __launch_bounds__(256, 2) void k_gemm1(const float* __restrict__ X,
                                                  const float* __restrict__ B,
                                                  uint32_t* __restrict__ O) {
    extern __shared__ char smem[];
    int tid = threadIdx.x;
    int wid = tid >> 5;
    int lane = tid & 31;
    int m0 = blockIdx.x * 64;

    load_w_smem(smem, 0, tid);
    for (int p = tid; p < 64 * 32; p += 256) {
        int row = p >> 5;
        int c4 = (p & 31) * 4;
        int gr = m0 + row;
        if (gr >= N_NODES) gr = 0;
        float4 v = *(const float4*)(X + (size_t)gr * CH + c4);
        *(uint2*)(smem + SM_A + row * 272 + c4 * 2) =
            make_uint2(pack_bf2(v.x, v.y), pack_bf2(v.z, v.w));
    }
    __syncthreads();
    mma_phase(smem, m0, B, O, wid, lane);
}

// ---------------- layers 2/3 GEMM: bf16 activation input ----------------
__global__ __launch_bounds__(256, 2) void k_gemm(const uint32_t* __restrict__ A,
                                                 int layer,
                                                 const float* __restrict__ B,
                                                 uint32_t* __restrict__ O) {
    extern __shared__ char smem[];
    int tid = threadIdx.x;
    int wid = tid >> 5;
    int lane = tid & 31;
    int m0 = blockIdx.x * 64;

    load_w_smem(smem, layer, tid);
    for (int p = tid; p < 64 * 16; p += 256) {
        int row = p >> 4;
        int j = p & 15;
        int gr = m0 + row;
        if (gr >= N_NODES) gr = 0;
        uint4 v = ((const uint4*)(A + (size_t)gr * 64))[j];
        *(uint4*)(smem + SM_A + row * 272 + j * 16) = v;
    }
    __syncthreads();
    mma_phase(smem, m0, B, O, wid, lane);
}

// ---------------- CSR gather aggregation: 2 degree-matched nodes per warp ----------------
// lanes 0-15 -> perm[2p], lanes 16-31 -> perm[2p+1]; each lane = 8 channels (uint4).
__global__ __launch_bounds__(256) void k_agg(const uint32_t* __restrict__ M,
                                             uint32_t* __restrict__ A,
                                             const int* __restrict__ batch,
                                             int mode) {
    int pair = blockIdx.x * 8 + (threadIdx.x >> 5);
    int lane = threadIdx.x & 31;
    int half = lane >> 4;
    int hl   = lane & 15;
    int idx  = pair * 2 + half;
    if (idx >= N_NODES) return;
    int node = g_perm[idx];
    const uint4* H4 = (const uint4*)M + hl;

    uint4 hn = ldcg_u4(H4 + (size_t)node * 16);
    float a0 = bflo(hn.x), a1 = bfhi(hn.x), a2 = bflo(hn.y), a3 = bfhi(hn.y);
    float a4 = bflo(hn.z), a5 = bfhi(hn.z), a6 = bflo(hn.w), a7 = bfhi(hn.w);

    int e   = g_rowstart[node];
    int end = g_rowstart[node + 1];

    for (; e + 4 <= end; e += 4) {
        int s0 = g_col[e + 0], s1 = g_col[e + 1], s2 = g_col[e + 2], s3 = g_col[e + 3];
        uint4 v0 = ldcg_u4(H4 + (size_t)s0 * 16);
        uint4 v1 = ldcg_u4(H4 + (size_t)s1 * 16);
        uint4 v2 = ldcg_u4(H4 + (size_t)s2 * 16);
        uint4 v3 = ldcg_u4(H4 + (size_t)s3 * 16);
        a0 += (bflo(v0.x) + bflo(v1.x)) + (bflo(v2.x) + bflo(v3.x));
        a1 += (bfhi(v0.x) + bfhi(v1.x)) + (bfhi(v2.x) + bfhi(v3.x));
        a2 += (bflo(v0.y) + bflo(v1.y)) + (bflo(v2.y) + bflo(v3.y));
        a3 += (bfhi(v0.y) + bfhi(v1.y)) + (bfhi(v2.y) + bfhi(v3.y));
        a4 += (bflo(v0.z) + bflo(v1.z)) + (bflo(v2.z) + bflo(v3.z));
        a5 += (bfhi(v0.z) + bfhi(v1.z)) + (bfhi(v2.z) + bfhi(v3.z));
        a6 += (bflo(v0.w) + bflo(v1.w)) + (bflo(v2.w) + bflo(v3.w));
        a7 += (bfhi(v0.w) + bfhi(v1.w)) + (bfhi(v2.w) + bfhi(v3.w));
    }
    for (; e < end; e++) {
        uint4 v = ldcg_u4(H4 + (size_t)g_col[e] * 16);
        a0 += bflo(v.x); a1 += bfhi(v.x);
        a2 += bflo(v.y); a3 += bfhi(v.y);
        a4 += bflo(v.z); a5 += bfhi(v.z);
        a6 += bflo(v.w); a7 += bfhi(v.w);
    }

    float dn = g_dinv[node];
    a0 *= dn; a1 *= dn; a2 *= dn; a3 *= dn;
    a4 *= dn; a5 *= dn; a6 *= dn; a7 *= dn;

    if (mode == 0) {
        a0 = fmaxf(a0, 0.f); a1 = fmaxf(a1, 0.f);
        a2 = fmaxf(a2, 0.f); a3 = fmaxf(a3, 0.f);
        a4 = fmaxf(a4, 0.f); a5 = fmaxf(a5, 0.f);
        a6 = fmaxf(a6, 0.f); a7 = fmaxf(a7, 0.f);
        uint4 o;
        o.x = pack_bf2(a0, a1); o.y = pack_bf2(a2, a3);
        o.z = pack_bf2(a4, a5); o.w = pack_bf2(a6, a7);
        ((uint4*)A)[(size_t)node * 16 + hl] = o;
    } else {
        int g = batch[node];
        float* dst = &g_pool[g * CH + hl * 8];
        asm volatile("red.global.add.v4.f32 [%0], {%1,%2,%3,%4};"
                     :: "l"(dst), "f"(a0), "f"(a1), "f"(a2), "f"(a3) : "memory");
        asm volatile("red.global.add.v4.f32 [%0], {%1,%2,%3,%4};"
                     :: "l"(dst + 4), "f"(a4), "f"(a5), "f"(a6), "f"(a7) : "memory");
        if (hl == 0) atomicAdd(&g_cnt[g], 1.0f);
    }
}

// ---------------- final projection ----------------
__global__ void k_final(const float* __restrict__ Wp, const float* __restrict__ bp,
                        float* __restrict__ out) {
    int g = blockIdx.x;
    int j = threadIdx.x;
    float inv = 1.0f / fmaxf(g_cnt[g], 1.0f);
    float acc = bp[j];
    #pragma unroll 4
    for (int c = 0; c < CH; c++)
        acc += g_pool[g * CH + c] * inv * Wp[c * OUTC + j];
    out[g * OUTC + j] = acc;
}

// ---------------- launch ----------------
extern "C" void kernel_launch(void* const* d_in, const int* in_sizes, int n_in,
                              void* d_out, int out_size) {
    const float* x   = (const float*)d_in[0];
    const int*   ei  = (const int*)d_in[1];
    const int*   bat = (const int*)d_in[2];
    const float* W1 = (const float*)d_in[3];
    const float* b1 = (const float*)d_in[4];
    const float* W2 = (const float*)d_in[5];
    const float* b2 = (const float*)d_in[6];
    const float* W3 = (const float*)d_in[7];
    const float* b3 = (const float*)d_in[8];
    const float* Wp = (const float*)d_in[9];
    const float* bp = (const float*)d_in[10];
    float* out = (float*)d_out;

    void *pm, *pa;
    cudaGetSymbolAddress(&pm, g_msg);
    cudaGetSymbolAddress(&pa, g_act);
    uint32_t* msg = (uint32_t*)pm;
    uint32_t* act = (uint32_t*)pa;

    static cudaStream_t sB = nullptr, sC = nullptr;
    static cudaEvent_t ev_fork = nullptr, ev_cnt = nullptr, ev_csr = nullptr, ev_perm = nullptr;
    if (sB == nullptr) {
        cudaFuncSetAttribute(k_gemm1, cudaFuncAttributeMaxDynamicSharedMemorySize, SM_TOTAL);
        cudaFuncSetAttribute(k_gemm, cudaFuncAttributeMaxDynamicSharedMemorySize, SM_TOTAL);
        cudaStreamCreateWithFlags(&sB, cudaStreamNonBlocking);
        cudaStreamCreateWithFlags(&sC, cudaStreamNonBlocking);
        cudaEventCreateWithFlags(&ev_fork, cudaEventDisableTiming);
        cudaEventCreateWithFlags(&ev_cnt, cudaEventDisableTiming);
        cudaEventCreateWithFlags(&ev_csr, cudaEventDisableTiming);
        cudaEventCreateWithFlags(&ev_perm, cudaEventDisableTiming);
    }

    int nb_nodes = (N_NODES + 255) / 256;
    int nb_e4    = (N_EDGES / 4 + 255) / 256;
    int nb_pair8 = (N_NODES / 2 + 7) / 8;
    int nb_gemm  = (N_NODES + 63) / 64;
    int nb_w3    = (3 * CH * CH + 255) / 256;

    // stream B: CSR build
    cudaEventRecord(ev_fork, 0);
    cudaStreamWaitEvent(sB, ev_fork, 0);
    k_zero  <<<nb_nodes, 256, 0, sB>>>();
    k_count <<<nb_e4,    256, 0, sB>>>(ei);
    k_dinv  <<<nb_nodes, 256, 0, sB>>>();
    cudaEventRecord(ev_cnt, sB);
    k_scanlb<<<NSCAN_BLOCKS, 512, 0, sB>>>();
    k_fill  <<<nb_e4,    256, 0, sB>>>(ei);
    cudaEventRecord(ev_csr, sB);

    // stream C: degree-sort permutation (needs only counts)
    cudaStreamWaitEvent(sC, ev_cnt, 0);
    k_dhist<<<nb_nodes, 256, 0, sC>>>();
    k_dscan<<<1, 32, 0, sC>>>();
    k_perm <<<nb_nodes, 256, 0, sC>>>();
    cudaEventRecord(ev_perm, sC);

    // main stream
    k_wconv3<<<nb_w3, 256>>>(W1, W2, W3);
    cudaStreamWaitEvent(0, ev_cnt, 0);    // dinv ready
    k_gemm1<<<nb_gemm, 256, SM_TOTAL>>>(x, b1, msg);   // overlaps scan+fill
    cudaStreamWaitEvent(0, ev_csr, 0);
    cudaStreamWaitEvent(0, ev_perm, 0);

    k_agg<<<nb_pair8, 256>>>(msg, act, bat, 0);
    k_gemm<<<nb_gemm, 256, SM_TOTAL>>>(act, 1, b2, msg);
    k_agg<<<nb_pair8, 256>>>(msg, act, bat, 0);
    k_gemm<<<nb_gemm, 256, SM_TOTAL>>>(act, 2, b3, msg);
    k_agg<<<nb_pair8, 256>>>(msg, nullptr, bat, 1);    // fused pooling
    k_final<<<NG, OUTC>>>(Wp, bp, out);
}

// round 15
// speedup vs baseline: 1.1153x; 1.1153x over previous
#include <cuda_runtime.h>
#include <cuda_bf16.h>
#include <math.h>
#include <stdint.h>

#define N_NODES 100000
#define N_EDGES 1600000
#define CH 128
#define OUTC 64
#define NG 64

// ---------------- scratch (static device globals; no allocation) ----------------
__device__ __align__(16) uint32_t g_msg[N_NODES * 64];  // messages dinv*(h+b), bf16x2
__device__ __align__(16) uint32_t g_act[N_NODES * 64];  // relu'd activations, bf16x2
__device__ float g_dinv[N_NODES];
__device__ int   g_counts[N_NODES];
__device__ int   g_rowstart[N_NODES + 1];
__device__ int   g_rank[N_EDGES];
__device__ int   g_col[N_EDGES];
__device__ int   g_bsum[256];
__device__ int   g_boff[256];
__device__ __align__(16) __nv_bfloat16 g_wh[3 * CH * CH];  // W^T hi, [layer][n][k]
__device__ __align__(16) __nv_bfloat16 g_wl[3 * CH * CH];  // W^T lo
__device__ __align__(16) float g_pool[NG * CH];
__device__ float g_cnt[NG];

__device__ __forceinline__ float bflo(uint32_t u) {
    return __bfloat162float(__ushort_as_bfloat16((unsigned short)(u & 0xFFFF)));
}
__device__ __forceinline__ float bfhi(uint32_t u) {
    return __bfloat162float(__ushort_as_bfloat16((unsigned short)(u >> 16)));
}
__device__ __forceinline__ uint32_t pack_bf2(float a, float b) {
    __nv_bfloat16 x = __float2bfloat16(a), y = __float2bfloat16(b);
    return (uint32_t)__bfloat16_as_ushort(x) | ((uint32_t)__bfloat16_as_ushort(y) << 16);
}
__device__ __forceinline__ uint4 ldcg_u4(const uint4* p) {
    uint4 v;
    asm volatile("ld.global.cg.v4.u32 {%0,%1,%2,%3}, [%4];"
                 : "=r"(v.x), "=r"(v.y), "=r"(v.z), "=r"(v.w) : "l"(p));
    return v;
}

// ---------------- zero per-call state ----------------
__global__ void k_zero() {
    int i = blockIdx.x * blockDim.x + threadIdx.x;
    if (i < N_NODES) g_counts[i] = 0;
    if (i < NG * CH) g_pool[i] = 0.f;
    if (i < NG)      g_cnt[i] = 0.f;
}

// ---------------- degree histogram + per-edge rank (atomic return value) ----------------
__global__ void k_count(const int* __restrict__ ei) {
    int e4 = blockIdx.x * blockDim.x + threadIdx.x;
    if (e4 < N_EDGES / 4) {
        int4 d = *(const int4*)(ei + N_EDGES + e4 * 4);
        int4 r;
        r.x = atomicAdd(&g_counts[d.x], 1);
        r.y = atomicAdd(&g_counts[d.y], 1);
        r.z = atomicAdd(&g_counts[d.z], 1);
        r.w = atomicAdd(&g_counts[d.w], 1);
        *(int4*)(g_rank + e4 * 4) = r;
    }
}

// ---------------- dinv (only needs counts; unblocks gemm1 early) ----------------
__global__ void k_dinv() {
    int i = blockIdx.x * blockDim.x + threadIdx.x;
    if (i < N_NODES) g_dinv[i] = rsqrtf((float)g_counts[i] + 1.0f);
}

// ---------------- multi-block scan pass 1 ----------------
__global__ __launch_bounds__(512) void k_scan1() {
    __shared__ int sh[512];
    int i = blockIdx.x * 512 + threadIdx.x;
    int v = (i < N_NODES) ? g_counts[i] : 0;
    sh[threadIdx.x] = v;
    __syncthreads();
    #pragma unroll
    for (int d = 1; d < 512; d <<= 1) {
        int t = (threadIdx.x >= d) ? sh[threadIdx.x - d] : 0;
        __syncthreads();
        sh[threadIdx.x] += t;
        __syncthreads();
    }
    if (i < N_NODES) g_rowstart[i] = sh[threadIdx.x] - v;
    if (threadIdx.x == 511) g_bsum[blockIdx.x] = sh[511];
}

// ---------------- pass 2 ----------------
__global__ __launch_bounds__(256) void k_scan2(int nblk) {
    __shared__ int sh[256];
    int t = threadIdx.x;
    int v = (t < nblk) ? g_bsum[t] : 0;
    sh[t] = v;
    __syncthreads();
    #pragma unroll
    for (int d = 1; d < 256; d <<= 1) {
        int tv = (t >= d) ? sh[t - d] : 0;
        __syncthreads();
        sh[t] += tv;
        __syncthreads();
    }
    g_boff[t] = sh[t] - v;
}

// ---------------- pass 3 ----------------
__global__ void k_scan3() {
    int i = blockIdx.x * blockDim.x + threadIdx.x;
    if (i < N_NODES) g_rowstart[i] += g_boff[i >> 9];
    if (i == 0) g_rowstart[N_NODES] = N_EDGES;
}

// ---------------- CSR fill by rank (no atomics) ----------------
__global__ void k_fill(const int* __restrict__ ei) {
    int e4 = blockIdx.x * blockDim.x + threadIdx.x;
    if (e4 < N_EDGES / 4) {
        int4 s = *(const int4*)(ei + e4 * 4);
        int4 d = *(const int4*)(ei + N_EDGES + e4 * 4);
        int4 r = *(const int4*)(g_rank + e4 * 4);
        g_col[g_rowstart[d.x] + r.x] = s.x;
        g_col[g_rowstart[d.y] + r.y] = s.y;
        g_col[g_rowstart[d.z] + r.z] = s.z;
        g_col[g_rowstart[d.w] + r.w] = s.w;
    }
}

// ---------------- weight convert, all 3 layers ----------------
__global__ void k_wconv3(const float* __restrict__ W1, const float* __restrict__ W2,
                         const float* __restrict__ W3) {
    int i = blockIdx.x * blockDim.x + threadIdx.x;   // i = l*16384 + n*128 + k
    if (i < 3 * CH * CH) {
        int l = i >> 14;
        int n = (i >> 7) & 127, k = i & 127;
        const float* W = (l == 0) ? W1 : (l == 1) ? W2 : W3;
        float w = W[k * CH + n];
        __nv_bfloat16 h = __float2bfloat16(w);
        __nv_bfloat16 lo = __float2bfloat16(w - __bfloat162float(h));
        g_wh[i] = h;
        g_wl[i] = lo;
    }
}

// ---------------- shared GEMM machinery ----------------
#define SM_A  0
#define SM_BH (64 * 272)
#define SM_BL (SM_BH + 128 * 272)
#define SM_TOTAL (SM_BL + 128 * 272)   // 87040 B

__device__ __forceinline__ void mma16816(float* c, const uint32_t* a, const uint32_t* b) {
    asm volatile("mma.sync.aligned.m16n8k16.row.col.f32.bf16.bf16.f32 "
                 "{%0,%1,%2,%3}, {%4,%5,%6,%7}, {%8,%9}, {%0,%1,%2,%3};"
                 : "+f"(c[0]), "+f"(c[1]), "+f"(c[2]), "+f"(c[3])
                 : "r"(a[0]), "r"(a[1]), "r"(a[2]), "r"(a[3]), "r"(b[0]), "r"(b[1]));
}

__device__ __forceinline__ void load_w_smem(char* smem, int layer, int tid) {
    const __nv_bfloat16* wh = g_wh + layer * CH * CH;
    const __nv_bfloat16* wl = g_wl + layer * CH * CH;
    for (int p = tid; p < 128 * 16; p += 256) {
        int n = p >> 4;
        int k8 = (p & 15) * 8;
        uint4 vh = *(const uint4*)(wh + n * CH + k8);
        uint4 vl = *(const uint4*)(wl + n * CH + k8);
        *(uint4*)(smem + SM_BH + n * 272 + k8 * 2) = vh;
        *(uint4*)(smem + SM_BL + n * 272 + k8 * 2) = vl;
    }
}

// MMA + epilogue: O[r][c] = dinv[r]*(A@W + b), packed bf16x2 messages
__device__ __forceinline__ void mma_phase(char* smem, int m0, const float* __restrict__ B,
                                          uint32_t* __restrict__ O, int wid, int lane) {
    int m_w = (wid & 1) * 32;
    int n_w = (wid >> 1) * 32;
    float acc[2][4][4];
    #pragma unroll
    for (int mt = 0; mt < 2; mt++)
        #pragma unroll
        for (int nt = 0; nt < 4; nt++)
            #pragma unroll
            for (int j = 0; j < 4; j++) acc[mt][nt][j] = 0.f;

    int q = lane >> 2;
    int km = (lane & 3) * 2;

    #pragma unroll
    for (int ks = 0; ks < 8; ks++) {
        int k0 = ks * 16;
        uint32_t ah[2][4], bh[4][2], bl[4][2];
        #pragma unroll
        for (int mt = 0; mt < 2; mt++) {
            int r = m_w + mt * 16 + q;
            const char* pa = smem + SM_A + r * 272 + (k0 + km) * 2;
            ah[mt][0] = *(const uint32_t*)(pa);
            ah[mt][1] = *(const uint32_t*)(pa + 8 * 272);
            ah[mt][2] = *(const uint32_t*)(pa + 16);
            ah[mt][3] = *(const uint32_t*)(pa + 8 * 272 + 16);
        }
        #pragma unroll
        for (int nt = 0; nt < 4; nt++) {
            int n = n_w + nt * 8 + q;
            const char* pb = smem + n * 272 + (k0 + km) * 2;
            bh[nt][0] = *(const uint32_t*)(pb + SM_BH);
            bh[nt][1] = *(const uint32_t*)(pb + SM_BH + 16);
            bl[nt][0] = *(const uint32_t*)(pb + SM_BL);
            bl[nt][1] = *(const uint32_t*)(pb + SM_BL + 16);
        }
        #pragma unroll
        for (int mt = 0; mt < 2; mt++)
            #pragma unroll
            for (int nt = 0; nt < 4; nt++) {
                mma16816(acc[mt][nt], ah[mt], bh[nt]);
                mma16816(acc[mt][nt], ah[mt], bl[nt]);
            }
    }

    #pragma unroll
    for (int nt = 0; nt < 4; nt++) {
        int c = n_w + nt * 8 + km;
        float bx = __ldg(B + c), by = __ldg(B + c + 1);
        #pragma unroll
        for (int mt = 0; mt < 2; mt++) {
            int r0 = m0 + m_w + mt * 16 + q;
            if (r0 < N_NODES) {
                float dr = g_dinv[r0];
                O[(size_t)r0 * 64 + (c >> 1)] =
                    pack_bf2(dr * (acc[mt][nt][0] + bx), dr * (acc[mt][nt][1] + by));
            }
            int r1 = r0 + 8;
            if (r1 < N_NODES) {
                float dr = g_dinv[r1];
                O[(size_t)r1 * 64 + (c >> 1)] =
                    pack_bf2(dr * (acc[mt][nt][2] + bx), dr * (acc[mt][nt][3] + by));
            }
        }
    }
}

// ---------------- layer 1 GEMM: fp32 input -> bf16 A ----------------
__global__ __launch_bounds__(256, 2) void k_gemm1(const float* __restrict__ X,
                                                  const float* __restrict__ B,
                                                  uint32_t* __restrict__ O) {
    extern __shared__ char smem[];
    int tid = threadIdx.x;
    int wid = tid >> 5;
    int lane = tid & 31;
    int m0 = blockIdx.x * 64;

    load_w_smem(smem, 0, tid);
    for (int p = tid; p < 64 * 32; p += 256) {
        int row = p >> 5;
        int c4 = (p & 31) * 4;
        int gr = m0 + row;
        if (gr >= N_NODES) gr = 0;
        float4 v = *(const float4*)(X + (size_t)gr * CH + c4);
        *(uint2*)(smem + SM_A + row * 272 + c4 * 2) =
            make_uint2(pack_bf2(v.x, v.y), pack_bf2(v.z, v.w));
    }
    __syncthreads();
    mma_phase(smem, m0, B, O, wid, lane);
}

// ---------------- layers 2/3 GEMM: bf16 activation input ----------------
__global__ __launch_bounds__(256, 2) void k_gemm(const uint32_t* __restrict__ A,
                                                 int layer,
                                                 const float* __restrict__ B,
                                                 uint32_t* __restrict__ O) {
    extern __shared__ char smem[];
    int tid = threadIdx.x;
    int wid = tid >> 5;
    int lane = tid & 31;
    int m0 = blockIdx.x * 64;

    load_w_smem(smem, layer, tid);
    for (int p = tid; p < 64 * 16; p += 256) {
        int row = p >> 4;
        int j = p & 15;
        int gr = m0 + row;
        if (gr >= N_NODES) gr = 0;
        uint4 v = ((const uint4*)(A + (size_t)gr * 64))[j];
        *(uint4*)(smem + SM_A + row * 272 + j * 16) = v;
    }
    __syncthreads();
    mma_phase(smem, m0, B, O, wid, lane);
}

// ---------------- CSR gather aggregation: 2 nodes per warp, LDG.128 ----------------
// lanes 0-15 -> node 2p, lanes 16-31 -> node 2p+1; each lane = 8 channels (uint4).
__global__ __launch_bounds__(256) void k_agg(const uint32_t* __restrict__ M,
                                             uint32_t* __restrict__ A,
                                             const int* __restrict__ batch,
                                             int mode) {
    int pair = blockIdx.x * 8 + (threadIdx.x >> 5);
    int lane = threadIdx.x & 31;
    int half = lane >> 4;
    int hl   = lane & 15;
    int node = pair * 2 + half;
    if (node >= N_NODES) return;
    const uint4* H4 = (const uint4*)M + hl;

    uint4 hn = ldcg_u4(H4 + (size_t)node * 16);
    float a0 = bflo(hn.x), a1 = bfhi(hn.x), a2 = bflo(hn.y), a3 = bfhi(hn.y);
    float a4 = bflo(hn.z), a5 = bfhi(hn.z), a6 = bflo(hn.w), a7 = bfhi(hn.w);

    int e   = g_rowstart[node];
    int end = g_rowstart[node + 1];

    for (; e + 4 <= end; e += 4) {
        int s0 = g_col[e + 0], s1 = g_col[e + 1], s2 = g_col[e + 2], s3 = g_col[e + 3];
        uint4 v0 = ldcg_u4(H4 + (size_t)s0 * 16);
        uint4 v1 = ldcg_u4(H4 + (size_t)s1 * 16);
        uint4 v2 = ldcg_u4(H4 + (size_t)s2 * 16);
        uint4 v3 = ldcg_u4(H4 + (size_t)s3 * 16);
        a0 += (bflo(v0.x) + bflo(v1.x)) + (bflo(v2.x) + bflo(v3.x));
        a1 += (bfhi(v0.x) + bfhi(v1.x)) + (bfhi(v2.x) + bfhi(v3.x));
        a2 += (bflo(v0.y) + bflo(v1.y)) + (bflo(v2.y) + bflo(v3.y));
        a3 += (bfhi(v0.y) + bfhi(v1.y)) + (bfhi(v2.y) + bfhi(v3.y));
        a4 += (bflo(v0.z) + bflo(v1.z)) + (bflo(v2.z) + bflo(v3.z));
        a5 += (bfhi(v0.z) + bfhi(v1.z)) + (bfhi(v2.z) + bfhi(v3.z));
        a6 += (bflo(v0.w) + bflo(v1.w)) + (bflo(v2.w) + bflo(v3.w));
        a7 += (bfhi(v0.w) + bfhi(v1.w)) + (bfhi(v2.w) + bfhi(v3.w));
    }
    for (; e < end; e++) {
        uint4 v = ldcg_u4(H4 + (size_t)g_col[e] * 16);
        a0 += bflo(v.x); a1 += bfhi(v.x);
        a2 += bflo(v.y); a3 += bfhi(v.y);
        a4 += bflo(v.z); a5 += bfhi(v.z);
        a6 += bflo(v.w); a7 += bfhi(v.w);
    }

    float dn = g_dinv[node];
    a0 *= dn; a1 *= dn; a2 *= dn; a3 *= dn;
    a4 *= dn; a5 *= dn; a6 *= dn; a7 *= dn;

    if (mode == 0) {
        a0 = fmaxf(a0, 0.f); a1 = fmaxf(a1, 0.f);
        a2 = fmaxf(a2, 0.f); a3 = fmaxf(a3, 0.f);
        a4 = fmaxf(a4, 0.f); a5 = fmaxf(a5, 0.f);
        a6 = fmaxf(a6, 0.f); a7 = fmaxf(a7, 0.f);
        uint4 o;
        o.x = pack_bf2(a0, a1); o.y = pack_bf2(a2, a3);
        o.z = pack_bf2(a4, a5); o.w = pack_bf2(a6, a7);
        ((uint4*)A)[(size_t)node * 16 + hl] = o;
    } else {
        int g = batch[node];
        float* dst = &g_pool[g * CH + hl * 8];
        asm volatile("red.global.add.v4.f32 [%0], {%1,%2,%3,%4};"
                     :: "l"(dst), "f"(a0), "f"(a1), "f"(a2), "f"(a3) : "memory");
        asm volatile("red.global.add.v4.f32 [%0], {%1,%2,%3,%4};"
                     :: "l"(dst + 4), "f"(a4), "f"(a5), "f"(a6), "f"(a7) : "memory");
        if (hl == 0) atomicAdd(&g_cnt[g], 1.0f);
    }
}

// ---------------- final projection ----------------
__global__ void k_final(const float* __restrict__ Wp, const float* __restrict__ bp,
                        float* __restrict__ out) {
    int g = blockIdx.x;
    int j = threadIdx.x;
    float inv = 1.0f / fmaxf(g_cnt[g], 1.0f);
    float acc = bp[j];
    #pragma unroll 4
    for (int c = 0; c < CH; c++)
        acc += g_pool[g * CH + c] * inv * Wp[c * OUTC + j];
    out[g * OUTC + j] = acc;
}

// ---------------- launch ----------------
extern "C" void kernel_launch(void* const* d_in, const int* in_sizes, int n_in,
                              void* d_out, int out_size) {
    const float* x   = (const float*)d_in[0];
    const int*   ei  = (const int*)d_in[1];
    const int*   bat = (const int*)d_in[2];
    const float* W1 = (const float*)d_in[3];
    const float* b1 = (const float*)d_in[4];
    const float* W2 = (const float*)d_in[5];
    const float* b2 = (const float*)d_in[6];
    const float* W3 = (const float*)d_in[7];
    const float* b3 = (const float*)d_in[8];
    const float* Wp = (const float*)d_in[9];
    const float* bp = (const float*)d_in[10];
    float* out = (float*)d_out;

    void *pm, *pa;
    cudaGetSymbolAddress(&pm, g_msg);
    cudaGetSymbolAddress(&pa, g_act);
    uint32_t* msg = (uint32_t*)pm;
    uint32_t* act = (uint32_t*)pa;

    static cudaStream_t sB = nullptr;
    static cudaEvent_t ev_fork = nullptr, ev_dinv = nullptr, ev_csr = nullptr;
    if (sB == nullptr) {
        cudaFuncSetAttribute(k_gemm1, cudaFuncAttributeMaxDynamicSharedMemorySize, SM_TOTAL);
        cudaFuncSetAttribute(k_gemm, cudaFuncAttributeMaxDynamicSharedMemorySize, SM_TOTAL);
        cudaStreamCreateWithFlags(&sB, cudaStreamNonBlocking);
        cudaEventCreateWithFlags(&ev_fork, cudaEventDisableTiming);
        cudaEventCreateWithFlags(&ev_dinv, cudaEventDisableTiming);
        cudaEventCreateWithFlags(&ev_csr, cudaEventDisableTiming);
    }

    int nb_nodes = (N_NODES + 255) / 256;
    int nb_e4    = (N_EDGES / 4 + 255) / 256;
    int nb_pair8 = (N_NODES / 2 + 7) / 8;   // 2 nodes per warp, 8 warps per block
    int nb_gemm  = (N_NODES + 63) / 64;
    int nb_scan1 = (N_NODES + 511) / 512;   // 196
    int nb_w3    = (3 * CH * CH + 255) / 256;

    // side stream: CSR build; dinv early
    cudaEventRecord(ev_fork, 0);
    cudaStreamWaitEvent(sB, ev_fork, 0);
    k_zero <<<nb_nodes, 256, 0, sB>>>();
    k_count<<<nb_e4,    256, 0, sB>>>(ei);
    k_dinv <<<nb_nodes, 256, 0, sB>>>();
    cudaEventRecord(ev_dinv, sB);
    k_scan1<<<nb_scan1, 512, 0, sB>>>();
    k_scan2<<<1,        256, 0, sB>>>(nb_scan1);
    k_scan3<<<nb_nodes, 256, 0, sB>>>();
    k_fill <<<nb_e4,    256, 0, sB>>>(ei);
    cudaEventRecord(ev_csr, sB);

    // main stream
    k_wconv3<<<nb_w3, 256>>>(W1, W2, W3);
    cudaStreamWaitEvent(0, ev_dinv, 0);
    k_gemm1<<<nb_gemm, 256, SM_TOTAL>>>(x, b1, msg);       // overlaps scan+fill
    cudaStreamWaitEvent(0, ev_csr, 0);

    k_agg<<<nb_pair8, 256>>>(msg, act, bat, 0);
    k_gemm<<<nb_gemm, 256, SM_TOTAL>>>(act, 1, b2, msg);
    k_agg<<<nb_pair8, 256>>>(msg, act, bat, 0);
    k_gemm<<<nb_gemm, 256, SM_TOTAL>>>(act, 2, b3, msg);
    k_agg<<<nb_pair8, 256>>>(msg, nullptr, bat, 1);        // fused pooling
    k_final<<<NG, OUTC>>>(Wp, bp, out);
}

// round 16
// speedup vs baseline: 1.2320x; 1.1046x over previous
#include <cuda_runtime.h>
#include <cuda_bf16.h>
#include <math.h>
#include <stdint.h>

#define N_NODES 100000
#define N_EDGES 1600000
#define CH 128
#define OUTC 64
#define NG 64
#define NTILES ((N_NODES + 63) / 64)   // 1563
#define GEMM_GRID 296                  // 2 CTAs x 148 SMs, persistent

// ---------------- scratch (static device globals; no allocation) ----------------
__device__ __align__(16) uint32_t g_msg[N_NODES * 64];  // messages dinv*(h+b), bf16x2
__device__ __align__(16) uint32_t g_act[N_NODES * 64];  // relu'd activations, bf16x2
__device__ float g_dinv[N_NODES];
__device__ int   g_counts[N_NODES];
__device__ int   g_rowstart[N_NODES + 1];
__device__ int   g_rank[N_EDGES];
__device__ int   g_col[N_EDGES];
__device__ int   g_bsum[256];
__device__ int   g_boff[256];
__device__ __align__(16) __nv_bfloat16 g_wh[3 * CH * CH];  // W^T hi, [layer][n][k]
__device__ __align__(16) __nv_bfloat16 g_wl[3 * CH * CH];  // W^T lo
__device__ __align__(16) float g_pool[NG * CH];
__device__ float g_cnt[NG];

__device__ __forceinline__ float bflo(uint32_t u) {
    return __bfloat162float(__ushort_as_bfloat16((unsigned short)(u & 0xFFFF)));
}
__device__ __forceinline__ float bfhi(uint32_t u) {
    return __bfloat162float(__ushort_as_bfloat16((unsigned short)(u >> 16)));
}
__device__ __forceinline__ uint32_t pack_bf2(float a, float b) {
    __nv_bfloat16 x = __float2bfloat16(a), y = __float2bfloat16(b);
    return (uint32_t)__bfloat16_as_ushort(x) | ((uint32_t)__bfloat16_as_ushort(y) << 16);
}
__device__ __forceinline__ uint4 ldcg_u4(const uint4* p) {
    uint4 v;
    asm volatile("ld.global.cg.v4.u32 {%0,%1,%2,%3}, [%4];"
                 : "=r"(v.x), "=r"(v.y), "=r"(v.z), "=r"(v.w) : "l"(p));
    return v;
}

// ---------------- zero per-call state ----------------
__global__ void k_zero() {
    int i = blockIdx.x * blockDim.x + threadIdx.x;
    if (i < N_NODES) g_counts[i] = 0;
    if (i < NG * CH) g_pool[i] = 0.f;
    if (i < NG)      g_cnt[i] = 0.f;
}

// ---------------- degree histogram + per-edge rank ----------------
__global__ void k_count(const int* __restrict__ ei) {
    int e4 = blockIdx.x * blockDim.x + threadIdx.x;
    if (e4 < N_EDGES / 4) {
        int4 d = *(const int4*)(ei + N_EDGES + e4 * 4);
        int4 r;
        r.x = atomicAdd(&g_counts[d.x], 1);
        r.y = atomicAdd(&g_counts[d.y], 1);
        r.z = atomicAdd(&g_counts[d.z], 1);
        r.w = atomicAdd(&g_counts[d.w], 1);
        *(int4*)(g_rank + e4 * 4) = r;
    }
}

// ---------------- dinv ----------------
__global__ void k_dinv() {
    int i = blockIdx.x * blockDim.x + threadIdx.x;
    if (i < N_NODES) g_dinv[i] = rsqrtf((float)g_counts[i] + 1.0f);
}

// ---------------- multi-block scan pass 1 ----------------
__global__ __launch_bounds__(512) void k_scan1() {
    __shared__ int sh[512];
    int i = blockIdx.x * 512 + threadIdx.x;
    int v = (i < N_NODES) ? g_counts[i] : 0;
    sh[threadIdx.x] = v;
    __syncthreads();
    #pragma unroll
    for (int d = 1; d < 512; d <<= 1) {
        int t = (threadIdx.x >= d) ? sh[threadIdx.x - d] : 0;
        __syncthreads();
        sh[threadIdx.x] += t;
        __syncthreads();
    }
    if (i < N_NODES) g_rowstart[i] = sh[threadIdx.x] - v;
    if (threadIdx.x == 511) g_bsum[blockIdx.x] = sh[511];
}

// ---------------- pass 2 ----------------
__global__ __launch_bounds__(256) void k_scan2(int nblk) {
    __shared__ int sh[256];
    int t = threadIdx.x;
    int v = (t < nblk) ? g_bsum[t] : 0;
    sh[t] = v;
    __syncthreads();
    #pragma unroll
    for (int d = 1; d < 256; d <<= 1) {
        int tv = (t >= d) ? sh[t - d] : 0;
        __syncthreads();
        sh[t] += tv;
        __syncthreads();
    }
    g_boff[t] = sh[t] - v;
}

// ---------------- pass 3 ----------------
__global__ void k_scan3() {
    int i = blockIdx.x * blockDim.x + threadIdx.x;
    if (i < N_NODES) g_rowstart[i] += g_boff[i >> 9];
    if (i == 0) g_rowstart[N_NODES] = N_EDGES;
}

// ---------------- CSR fill by rank (no atomics) ----------------
__global__ void k_fill(const int* __restrict__ ei) {
    int e4 = blockIdx.x * blockDim.x + threadIdx.x;
    if (e4 < N_EDGES / 4) {
        int4 s = *(const int4*)(ei + e4 * 4);
        int4 d = *(const int4*)(ei + N_EDGES + e4 * 4);
        int4 r = *(const int4*)(g_rank + e4 * 4);
        g_col[g_rowstart[d.x] + r.x] = s.x;
        g_col[g_rowstart[d.y] + r.y] = s.y;
        g_col[g_rowstart[d.z] + r.z] = s.z;
        g_col[g_rowstart[d.w] + r.w] = s.w;
    }
}

// ---------------- weight convert, all 3 layers ----------------
__global__ void k_wconv3(const float* __restrict__ W1, const float* __restrict__ W2,
                         const float* __restrict__ W3) {
    int i = blockIdx.x * blockDim.x + threadIdx.x;
    if (i < 3 * CH * CH) {
        int l = i >> 14;
        int n = (i >> 7) & 127, k = i & 127;
        const float* W = (l == 0) ? W1 : (l == 1) ? W2 : W3;
        float w = W[k * CH + n];
        __nv_bfloat16 h = __float2bfloat16(w);
        __nv_bfloat16 lo = __float2bfloat16(w - __bfloat162float(h));
        g_wh[i] = h;
        g_wl[i] = lo;
    }
}

// ---------------- shared GEMM machinery ----------------
#define SM_A  0
#define SM_BH (64 * 272)
#define SM_BL (SM_BH + 128 * 272)
#define SM_TOTAL (SM_BL + 128 * 272)   // 87040 B

__device__ __forceinline__ void mma16816(float* c, const uint32_t* a, const uint32_t* b) {
    asm volatile("mma.sync.aligned.m16n8k16.row.col.f32.bf16.bf16.f32 "
                 "{%0,%1,%2,%3}, {%4,%5,%6,%7}, {%8,%9}, {%0,%1,%2,%3};"
                 : "+f"(c[0]), "+f"(c[1]), "+f"(c[2]), "+f"(c[3])
                 : "r"(a[0]), "r"(a[1]), "r"(a[2]), "r"(a[3]), "r"(b[0]), "r"(b[1]));
}

__device__ __forceinline__ void load_w_smem(char* smem, int layer, int tid) {
    const __nv_bfloat16* wh = g_wh + layer * CH * CH;
    const __nv_bfloat16* wl = g_wl + layer * CH * CH;
    for (int p = tid; p < 128 * 16; p += 256) {
        int n = p >> 4;
        int k8 = (p & 15) * 8;
        uint4 vh = *(const uint4*)(wh + n * CH + k8);
        uint4 vl = *(const uint4*)(wl + n * CH + k8);
        *(uint4*)(smem + SM_BH + n * 272 + k8 * 2) = vh;
        *(uint4*)(smem + SM_BL + n * 272 + k8 * 2) = vl;
    }
}

// MMA + epilogue: O[r][c] = dinv[r]*(A@W + b), packed bf16x2 messages
__device__ __forceinline__ void mma_phase(char* smem, int m0, const float* __restrict__ B,
                                          uint32_t* __restrict__ O, int wid, int lane) {
    int m_w = (wid & 1) * 32;
    int n_w = (wid >> 1) * 32;
    float acc[2][4][4];
    #pragma unroll
    for (int mt = 0; mt < 2; mt++)
        #pragma unroll
        for (int nt = 0; nt < 4; nt++)
            #pragma unroll
            for (int j = 0; j < 4; j++) acc[mt][nt][j] = 0.f;

    int q = lane >> 2;
    int km = (lane & 3) * 2;

    #pragma unroll
    for (int ks = 0; ks < 8; ks++) {
        int k0 = ks * 16;
        uint32_t ah[2][4], bh[4][2], bl[4][2];
        #pragma unroll
        for (int mt = 0; mt < 2; mt++) {
            int r = m_w + mt * 16 + q;
            const char* pa = smem + SM_A + r * 272 + (k0 + km) * 2;
            ah[mt][0] = *(const uint32_t*)(pa);
            ah[mt][1] = *(const uint32_t*)(pa + 8 * 272);
            ah[mt][2] = *(const uint32_t*)(pa + 16);
            ah[mt][3] = *(const uint32_t*)(pa + 8 * 272 + 16);
        }
        #pragma unroll
        for (int nt = 0; nt < 4; nt++) {
            int n = n_w + nt * 8 + q;
            const char* pb = smem + n * 272 + (k0 + km) * 2;
            bh[nt][0] = *(const uint32_t*)(pb + SM_BH);
            bh[nt][1] = *(const uint32_t*)(pb + SM_BH + 16);
            bl[nt][0] = *(const uint32_t*)(pb + SM_BL);
            bl[nt][1] = *(const uint32_t*)(pb + SM_BL + 16);
        }
        #pragma unroll
        for (int mt = 0; mt < 2; mt++)
            #pragma unroll
            for (int nt = 0; nt < 4; nt++) {
                mma16816(acc[mt][nt], ah[mt], bh[nt]);
                mma16816(acc[mt][nt], ah[mt], bl[nt]);
            }
    }

    #pragma unroll
    for (int nt = 0; nt < 4; nt++) {
        int c = n_w + nt * 8 + km;
        float bx = __ldg(B + c), by = __ldg(B + c + 1);
        #pragma unroll
        for (int mt = 0; mt < 2; mt++) {
            int r0 = m0 + m_w + mt * 16 + q;
            if (r0 < N_NODES) {
                float dr = g_dinv[r0];
                O[(size_t)r0 * 64 + (c >> 1)] =
                    pack_bf2(dr * (acc[mt][nt][0] + bx), dr * (acc[mt][nt][1] + by));
            }
            int r1 = r0 + 8;
            if (r1 < N_NODES) {
                float dr = g_dinv[r1];
                O[(size_t)r1 * 64 + (c >> 1)] =
                    pack_bf2(dr * (acc[mt][nt][2] + bx), dr * (acc[mt][nt][3] + by));
            }
        }
    }
}

// ---------------- persistent layer-1 GEMM: fp32 input -> bf16 A, weights loaded once ----------------
__global__ __launch_bounds__(256, 2) void k_gemm1(const float* __restrict__ X,
                                                  const float* __restrict__ B,
                                                  uint32_t* __restrict__ O) {
    extern __shared__ char smem[];
    int tid = threadIdx.x;
    int wid = tid >> 5;
    int lane = tid & 31;

    load_w_smem(smem, 0, tid);
    __syncthreads();

    for (int tile = blockIdx.x; tile < NTILES; tile += GEMM_GRID) {
        int m0 = tile * 64;
        for (int p = tid; p < 64 * 32; p += 256) {
            int row = p >> 5;
            int c4 = (p & 31) * 4;
            int gr = m0 + row;
            if (gr >= N_NODES) gr = 0;
            float4 v = *(const float4*)(X + (size_t)gr * CH + c4);
            *(uint2*)(smem + SM_A + row * 272 + c4 * 2) =
                make_uint2(pack_bf2(v.x, v.y), pack_bf2(v.z, v.w));
        }
        __syncthreads();
        mma_phase(smem, m0, B, O, wid, lane);
        __syncthreads();
    }
}

// ---------------- persistent layers-2/3 GEMM: bf16 activation input ----------------
__global__ __launch_bounds__(256, 2) void k_gemm(const uint32_t* __restrict__ A,
                                                 int layer,
                                                 const float* __restrict__ B,
                                                 uint32_t* __restrict__ O) {
    extern __shared__ char smem[];
    int tid = threadIdx.x;
    int wid = tid >> 5;
    int lane = tid & 31;

    load_w_smem(smem, layer, tid);
    __syncthreads();

    for (int tile = blockIdx.x; tile < NTILES; tile += GEMM_GRID) {
        int m0 = tile * 64;
        for (int p = tid; p < 64 * 16; p += 256) {
            int row = p >> 4;
            int j = p & 15;
            int gr = m0 + row;
            if (gr >= N_NODES) gr = 0;
            uint4 v = ((const uint4*)(A + (size_t)gr * 64))[j];
            *(uint4*)(smem + SM_A + row * 272 + j * 16) = v;
        }
        __syncthreads();
        mma_phase(smem, m0, B, O, wid, lane);
        __syncthreads();
    }
}

// ---------------- CSR gather aggregation: 2 nodes per warp, LDG.128 ----------------
__global__ __launch_bounds__(256) void k_agg(const uint32_t* __restrict__ M,
                                             uint32_t* __restrict__ A,
                                             const int* __restrict__ batch,
                                             int mode) {
    int pair = blockIdx.x * 8 + (threadIdx.x >> 5);
    int lane = threadIdx.x & 31;
    int half = lane >> 4;
    int hl   = lane & 15;
    int node = pair * 2 + half;
    if (node >= N_NODES) return;
    const uint4* H4 = (const uint4*)M + hl;

    uint4 hn = ldcg_u4(H4 + (size_t)node * 16);
    float a0 = bflo(hn.x), a1 = bfhi(hn.x), a2 = bflo(hn.y), a3 = bfhi(hn.y);
    float a4 = bflo(hn.z), a5 = bfhi(hn.z), a6 = bflo(hn.w), a7 = bfhi(hn.w);

    int e   = g_rowstart[node];
    int end = g_rowstart[node + 1];

    for (; e + 4 <= end; e += 4) {
        int s0 = g_col[e + 0], s1 = g_col[e + 1], s2 = g_col[e + 2], s3 = g_col[e + 3];
        uint4 v0 = ldcg_u4(H4 + (size_t)s0 * 16);
        uint4 v1 = ldcg_u4(H4 + (size_t)s1 * 16);
        uint4 v2 = ldcg_u4(H4 + (size_t)s2 * 16);
        uint4 v3 = ldcg_u4(H4 + (size_t)s3 * 16);
        a0 += (bflo(v0.x) + bflo(v1.x)) + (bflo(v2.x) + bflo(v3.x));
        a1 += (bfhi(v0.x) + bfhi(v1.x)) + (bfhi(v2.x) + bfhi(v3.x));
        a2 += (bflo(v0.y) + bflo(v1.y)) + (bflo(v2.y) + bflo(v3.y));
        a3 += (bfhi(v0.y) + bfhi(v1.y)) + (bfhi(v2.y) + bfhi(v3.y));
        a4 += (bflo(v0.z) + bflo(v1.z)) + (bflo(v2.z) + bflo(v3.z));
        a5 += (bfhi(v0.z) + bfhi(v1.z)) + (bfhi(v2.z) + bfhi(v3.z));
        a6 += (bflo(v0.w) + bflo(v1.w)) + (bflo(v2.w) + bflo(v3.w));
        a7 += (bfhi(v0.w) + bfhi(v1.w)) + (bfhi(v2.w) + bfhi(v3.w));
    }
    for (; e < end; e++) {
        uint4 v = ldcg_u4(H4 + (size_t)g_col[e] * 16);
        a0 += bflo(v.x); a1 += bfhi(v.x);
        a2 += bflo(v.y); a3 += bfhi(v.y);
        a4 += bflo(v.z); a5 += bfhi(v.z);
        a6 += bflo(v.w); a7 += bfhi(v.w);
    }

    float dn = g_dinv[node];
    a0 *= dn; a1 *= dn; a2 *= dn; a3 *= dn;
    a4 *= dn; a5 *= dn; a6 *= dn; a7 *= dn;

    if (mode == 0) {
        a0 = fmaxf(a0, 0.f); a1 = fmaxf(a1, 0.f);
        a2 = fmaxf(a2, 0.f); a3 = fmaxf(a3, 0.f);
        a4 = fmaxf(a4, 0.f); a5 = fmaxf(a5, 0.f);
        a6 = fmaxf(a6, 0.f); a7 = fmaxf(a7, 0.f);
        uint4 o;
        o.x = pack_bf2(a0, a1); o.y = pack_bf2(a2, a3);
        o.z = pack_bf2(a4, a5); o.w = pack_bf2(a6, a7);
        ((uint4*)A)[(size_t)node * 16 + hl] = o;
    } else {
        int g = batch[node];
        float* dst = &g_pool[g * CH + hl * 8];
        asm volatile("red.global.add.v4.f32 [%0], {%1,%2,%3,%4};"
                     :: "l"(dst), "f"(a0), "f"(a1), "f"(a2), "f"(a3) : "memory");
        asm volatile("red.global.add.v4.f32 [%0], {%1,%2,%3,%4};"
                     :: "l"(dst + 4), "f"(a4), "f"(a5), "f"(a6), "f"(a7) : "memory");
        if (hl == 0) atomicAdd(&g_cnt[g], 1.0f);
    }
}

// ---------------- final projection ----------------
__global__ void k_final(const float* __restrict__ Wp, const float* __restrict__ bp,
                        float* __restrict__ out) {
    int g = blockIdx.x;
    int j = threadIdx.x;
    float inv = 1.0f / fmaxf(g_cnt[g], 1.0f);
    float acc = bp[j];
    #pragma unroll 4
    for (int c = 0; c < CH; c++)
        acc += g_pool[g * CH + c] * inv * Wp[c * OUTC + j];
    out[g * OUTC + j] = acc;
}

// ---------------- launch ----------------
extern "C" void kernel_launch(void* const* d_in, const int* in_sizes, int n_in,
                              void* d_out, int out_size) {
    const float* x   = (const float*)d_in[0];
    const int*   ei  = (const int*)d_in[1];
    const int*   bat = (const int*)d_in[2];
    const float* W1 = (const float*)d_in[3];
    const float* b1 = (const float*)d_in[4];
    const float* W2 = (const float*)d_in[5];
    const float* b2 = (const float*)d_in[6];
    const float* W3 = (const float*)d_in[7];
    const float* b3 = (const float*)d_in[8];
    const float* Wp = (const float*)d_in[9];
    const float* bp = (const float*)d_in[10];
    float* out = (float*)d_out;

    void *pm, *pa;
    cudaGetSymbolAddress(&pm, g_msg);
    cudaGetSymbolAddress(&pa, g_act);
    uint32_t* msg = (uint32_t*)pm;
    uint32_t* act = (uint32_t*)pa;

    static cudaStream_t sB = nullptr;
    static cudaEvent_t ev_fork = nullptr, ev_dinv = nullptr, ev_csr = nullptr;
    if (sB == nullptr) {
        cudaFuncSetAttribute(k_gemm1, cudaFuncAttributeMaxDynamicSharedMemorySize, SM_TOTAL);
        cudaFuncSetAttribute(k_gemm, cudaFuncAttributeMaxDynamicSharedMemorySize, SM_TOTAL);
        cudaStreamCreateWithFlags(&sB, cudaStreamNonBlocking);
        cudaEventCreateWithFlags(&ev_fork, cudaEventDisableTiming);
        cudaEventCreateWithFlags(&ev_dinv, cudaEventDisableTiming);
        cudaEventCreateWithFlags(&ev_csr, cudaEventDisableTiming);
    }

    int nb_nodes = (N_NODES + 255) / 256;
    int nb_e4    = (N_EDGES / 4 + 255) / 256;
    int nb_pair8 = (N_NODES / 2 + 7) / 8;
    int nb_scan1 = (N_NODES + 511) / 512;   // 196
    int nb_w3    = (3 * CH * CH + 255) / 256;

    // side stream: CSR build; dinv early
    cudaEventRecord(ev_fork, 0);
    cudaStreamWaitEvent(sB, ev_fork, 0);
    k_zero <<<nb_nodes, 256, 0, sB>>>();
    k_count<<<nb_e4,    256, 0, sB>>>(ei);
    k_dinv <<<nb_nodes, 256, 0, sB>>>();
    cudaEventRecord(ev_dinv, sB);
    k_scan1<<<nb_scan1, 512, 0, sB>>>();
    k_scan2<<<1,        256, 0, sB>>>(nb_scan1);
    k_scan3<<<nb_nodes, 256, 0, sB>>>();
    k_fill <<<nb_e4,    256, 0, sB>>>(ei);
    cudaEventRecord(ev_csr, sB);

    // main stream
    k_wconv3<<<nb_w3, 256>>>(W1, W2, W3);
    cudaStreamWaitEvent(0, ev_dinv, 0);
    k_gemm1<<<GEMM_GRID, 256, SM_TOTAL>>>(x, b1, msg);     // overlaps scan+fill
    cudaStreamWaitEvent(0, ev_csr, 0);

    k_agg<<<nb_pair8, 256>>>(msg, act, bat, 0);
    k_gemm<<<GEMM_GRID, 256, SM_TOTAL>>>(act, 1, b2, msg);
    k_agg<<<nb_pair8, 256>>>(msg, act, bat, 0);
    k_gemm<<<GEMM_GRID, 256, SM_TOTAL>>>(act, 2, b3, msg);
    k_agg<<<nb_pair8, 256>>>(msg, nullptr, bat, 1);        // fused pooling
    k_final<<<NG, OUTC>>>(Wp, bp, out);
}

// round 17
// speedup vs baseline: 1.2846x; 1.0427x over previous
#include <cuda_runtime.h>
#include <cuda_bf16.h>
#include <math.h>
#include <stdint.h>

#define N_NODES 100000
#define N_EDGES 1600000
#define CH 128
#define OUTC 64
#define NG 64
#define NTILES ((N_NODES + 63) / 64)   // 1563
#define GEMM_GRID 296                  // 2 CTAs x 148 SMs, persistent

// ---------------- scratch (static device globals; no allocation) ----------------
__device__ __align__(16) uint32_t g_msg[N_NODES * 64];  // messages dinv*(h+b), bf16x2
__device__ __align__(16) uint32_t g_act[N_NODES * 64];  // relu'd activations, bf16x2
__device__ float g_dinv[N_NODES];
__device__ int   g_counts[N_NODES];
__device__ int   g_rowstart[N_NODES + 1];
__device__ int   g_rank[N_EDGES];
__device__ int   g_col[N_EDGES];
__device__ int   g_bsum[256];
__device__ int   g_boff[256];
__device__ __align__(16) __nv_bfloat16 g_wh[3 * CH * CH];  // W^T hi, [layer][n][k]
__device__ __align__(16) __nv_bfloat16 g_wl[3 * CH * CH];  // W^T lo
__device__ __align__(16) float g_pool[NG * CH];
__device__ float g_cnt[NG];

__device__ __forceinline__ float bflo(uint32_t u) {
    return __bfloat162float(__ushort_as_bfloat16((unsigned short)(u & 0xFFFF)));
}
__device__ __forceinline__ float bfhi(uint32_t u) {
    return __bfloat162float(__ushort_as_bfloat16((unsigned short)(u >> 16)));
}
__device__ __forceinline__ uint32_t pack_bf2(float a, float b) {
    __nv_bfloat16 x = __float2bfloat16(a), y = __float2bfloat16(b);
    return (uint32_t)__bfloat16_as_ushort(x) | ((uint32_t)__bfloat16_as_ushort(y) << 16);
}
__device__ __forceinline__ uint32_t badd2(uint32_t a, uint32_t b) {
    uint32_t r;
    asm("add.rn.bf16x2 %0, %1, %2;" : "=r"(r) : "r"(a), "r"(b));
    return r;
}
__device__ __forceinline__ uint4 ldcg_u4(const uint4* p) {
    uint4 v;
    asm volatile("ld.global.cg.v4.u32 {%0,%1,%2,%3}, [%4];"
                 : "=r"(v.x), "=r"(v.y), "=r"(v.z), "=r"(v.w) : "l"(p));
    return v;
}

// ---------------- zero per-call state ----------------
__global__ void k_zero() {
    int i = blockIdx.x * blockDim.x + threadIdx.x;
    if (i < N_NODES) g_counts[i] = 0;
    if (i < NG * CH) g_pool[i] = 0.f;
    if (i < NG)      g_cnt[i] = 0.f;
}

// ---------------- degree histogram + per-edge rank ----------------
__global__ void k_count(const int* __restrict__ ei) {
    int e4 = blockIdx.x * blockDim.x + threadIdx.x;
    if (e4 < N_EDGES / 4) {
        int4 d = *(const int4*)(ei + N_EDGES + e4 * 4);
        int4 r;
        r.x = atomicAdd(&g_counts[d.x], 1);
        r.y = atomicAdd(&g_counts[d.y], 1);
        r.z = atomicAdd(&g_counts[d.z], 1);
        r.w = atomicAdd(&g_counts[d.w], 1);
        *(int4*)(g_rank + e4 * 4) = r;
    }
}

// ---------------- dinv ----------------
__global__ void k_dinv() {
    int i = blockIdx.x * blockDim.x + threadIdx.x;
    if (i < N_NODES) g_dinv[i] = rsqrtf((float)g_counts[i] + 1.0f);
}

// ---------------- multi-block scan pass 1 ----------------
__global__ __launch_bounds__(512) void k_scan1() {
    __shared__ int sh[512];
    int i = blockIdx.x * 512 + threadIdx.x;
    int v = (i < N_NODES) ? g_counts[i] : 0;
    sh[threadIdx.x] = v;
    __syncthreads();
    #pragma unroll
    for (int d = 1; d < 512; d <<= 1) {
        int t = (threadIdx.x >= d) ? sh[threadIdx.x - d] : 0;
        __syncthreads();
        sh[threadIdx.x] += t;
        __syncthreads();
    }
    if (i < N_NODES) g_rowstart[i] = sh[threadIdx.x] - v;
    if (threadIdx.x == 511) g_bsum[blockIdx.x] = sh[511];
}

// ---------------- pass 2 ----------------
__global__ __launch_bounds__(256) void k_scan2(int nblk) {
    __shared__ int sh[256];
    int t = threadIdx.x;
    int v = (t < nblk) ? g_bsum[t] : 0;
    sh[t] = v;
    __syncthreads();
    #pragma unroll
    for (int d = 1; d < 256; d <<= 1) {
        int tv = (t >= d) ? sh[t - d] : 0;
        __syncthreads();
        sh[t] += tv;
        __syncthreads();
    }
    g_boff[t] = sh[t] - v;
}

// ---------------- pass 3 ----------------
__global__ void k_scan3() {
    int i = blockIdx.x * blockDim.x + threadIdx.x;
    if (i < N_NODES) g_rowstart[i] += g_boff[i >> 9];
    if (i == 0) g_rowstart[N_NODES] = N_EDGES;
}

// ---------------- CSR fill by rank (no atomics) ----------------
__global__ void k_fill(const int* __restrict__ ei) {
    int e4 = blockIdx.x * blockDim.x + threadIdx.x;
    if (e4 < N_EDGES / 4) {
        int4 s = *(const int4*)(ei + e4 * 4);
        int4 d = *(const int4*)(ei + N_EDGES + e4 * 4);
        int4 r = *(const int4*)(g_rank + e4 * 4);
        g_col[g_rowstart[d.x] + r.x] = s.x;
        g_col[g_rowstart[d.y] + r.y] = s.y;
        g_col[g_rowstart[d.z] + r.z] = s.z;
        g_col[g_rowstart[d.w] + r.w] = s.w;
    }
}

// ---------------- weight convert, all 3 layers ----------------
__global__ void k_wconv3(const float* __restrict__ W1, const float* __restrict__ W2,
                         const float* __restrict__ W3) {
    int i = blockIdx.x * blockDim.x + threadIdx.x;
    if (i < 3 * CH * CH) {
        int l = i >> 14;
        int n = (i >> 7) & 127, k = i & 127;
        const float* W = (l == 0) ? W1 : (l == 1) ? W2 : W3;
        float w = W[k * CH + n];
        __nv_bfloat16 h = __float2bfloat16(w);
        __nv_bfloat16 lo = __float2bfloat16(w - __bfloat162float(h));
        g_wh[i] = h;
        g_wl[i] = lo;
    }
}

// ---------------- shared GEMM machinery ----------------
#define SM_A  0
#define SM_BH (64 * 272)
#define SM_BL (SM_BH + 128 * 272)
#define SM_TOTAL (SM_BL + 128 * 272)   // 87040 B

__device__ __forceinline__ void mma16816(float* c, const uint32_t* a, const uint32_t* b) {
    asm volatile("mma.sync.aligned.m16n8k16.row.col.f32.bf16.bf16.f32 "
                 "{%0,%1,%2,%3}, {%4,%5,%6,%7}, {%8,%9}, {%0,%1,%2,%3};"
                 : "+f"(c[0]), "+f"(c[1]), "+f"(c[2]), "+f"(c[3])
                 : "r"(a[0]), "r"(a[1]), "r"(a[2]), "r"(a[3]), "r"(b[0]), "r"(b[1]));
}

__device__ __forceinline__ void load_w_smem(char* smem, int layer, int tid) {
    const __nv_bfloat16* wh = g_wh + layer * CH * CH;
    const __nv_bfloat16* wl = g_wl + layer * CH * CH;
    for (int p = tid; p < 128 * 16; p += 256) {
        int n = p >> 4;
        int k8 = (p & 15) * 8;
        uint4 vh = *(const uint4*)(wh + n * CH + k8);
        uint4 vl = *(const uint4*)(wl + n * CH + k8);
        *(uint4*)(smem + SM_BH + n * 272 + k8 * 2) = vh;
        *(uint4*)(smem + SM_BL + n * 272 + k8 * 2) = vl;
    }
}

// MMA + epilogue: O[r][c] = dinv[r]*(A@W + b), packed bf16x2 messages
__device__ __forceinline__ void mma_phase(char* smem, int m0, const float* __restrict__ B,
                                          uint32_t* __restrict__ O, int wid, int lane) {
    int m_w = (wid & 1) * 32;
    int n_w = (wid >> 1) * 32;
    float acc[2][4][4];
    #pragma unroll
    for (int mt = 0; mt < 2; mt++)
        #pragma unroll
        for (int nt = 0; nt < 4; nt++)
            #pragma unroll
            for (int j = 0; j < 4; j++) acc[mt][nt][j] = 0.f;

    int q = lane >> 2;
    int km = (lane & 3) * 2;

    #pragma unroll
    for (int ks = 0; ks < 8; ks++) {
        int k0 = ks * 16;
        uint32_t ah[2][4], bh[4][2], bl[4][2];
        #pragma unroll
        for (int mt = 0; mt < 2; mt++) {
            int r = m_w + mt * 16 + q;
            const char* pa = smem + SM_A + r * 272 + (k0 + km) * 2;
            ah[mt][0] = *(const uint32_t*)(pa);
            ah[mt][1] = *(const uint32_t*)(pa + 8 * 272);
            ah[mt][2] = *(const uint32_t*)(pa + 16);
            ah[mt][3] = *(const uint32_t*)(pa + 8 * 272 + 16);
        }
        #pragma unroll
        for (int nt = 0; nt < 4; nt++) {
            int n = n_w + nt * 8 + q;
            const char* pb = smem + n * 272 + (k0 + km) * 2;
            bh[nt][0] = *(const uint32_t*)(pb + SM_BH);
            bh[nt][1] = *(const uint32_t*)(pb + SM_BH + 16);
            bl[nt][0] = *(const uint32_t*)(pb + SM_BL);
            bl[nt][1] = *(const uint32_t*)(pb + SM_BL + 16);
        }
        #pragma unroll
        for (int mt = 0; mt < 2; mt++)
            #pragma unroll
            for (int nt = 0; nt < 4; nt++) {
                mma16816(acc[mt][nt], ah[mt], bh[nt]);
                mma16816(acc[mt][nt], ah[mt], bl[nt]);
            }
    }

    #pragma unroll
    for (int nt = 0; nt < 4; nt++) {
        int c = n_w + nt * 8 + km;
        float bx = __ldg(B + c), by = __ldg(B + c + 1);
        #pragma unroll
        for (int mt = 0; mt < 2; mt++) {
            int r0 = m0 + m_w + mt * 16 + q;
            if (r0 < N_NODES) {
                float dr = g_dinv[r0];
                O[(size_t)r0 * 64 + (c >> 1)] =
                    pack_bf2(dr * (acc[mt][nt][0] + bx), dr * (acc[mt][nt][1] + by));
            }
            int r1 = r0 + 8;
            if (r1 < N_NODES) {
                float dr = g_dinv[r1];
                O[(size_t)r1 * 64 + (c >> 1)] =
                    pack_bf2(dr * (acc[mt][nt][2] + bx), dr * (acc[mt][nt][3] + by));
            }
        }
    }
}

// ---------------- persistent layer-1 GEMM: fp32 input -> bf16 A, weights loaded once ----------------
__global__ __launch_bounds__(256, 2) void k_gemm1(const float* __restrict__ X,
                                                  const float* __restrict__ B,
                                                  uint32_t* __restrict__ O) {
    extern __shared__ char smem[];
    int tid = threadIdx.x;
    int wid = tid >> 5;
    int lane = tid & 31;

    load_w_smem(smem, 0, tid);
    __syncthreads();

    for (int tile = blockIdx.x; tile < NTILES; tile += GEMM_GRID) {
        int m0 = tile * 64;
        for (int p = tid; p < 64 * 32; p += 256) {
            int row = p >> 5;
            int c4 = (p & 31) * 4;
            int gr = m0 + row;
            if (gr >= N_NODES) gr = 0;
            float4 v = *(const float4*)(X + (size_t)gr * CH + c4);
            *(uint2*)(smem + SM_A + row * 272 + c4 * 2) =
                make_uint2(pack_bf2(v.x, v.y), pack_bf2(v.z, v.w));
        }
        __syncthreads();
        mma_phase(smem, m0, B, O, wid, lane);
        __syncthreads();
    }
}

// ---------------- persistent layers-2/3 GEMM: bf16 activation input ----------------
__global__ __launch_bounds__(256, 2) void k_gemm(const uint32_t* __restrict__ A,
                                                 int layer,
                                                 const float* __restrict__ B,
                                                 uint32_t* __restrict__ O) {
    extern __shared__ char smem[];
    int tid = threadIdx.x;
    int wid = tid >> 5;
    int lane = tid & 31;

    load_w_smem(smem, layer, tid);
    __syncthreads();

    for (int tile = blockIdx.x; tile < NTILES; tile += GEMM_GRID) {
        int m0 = tile * 64;
        for (int p = tid; p < 64 * 16; p += 256) {
            int row = p >> 4;
            int j = p & 15;
            int gr = m0 + row;
            if (gr >= N_NODES) gr = 0;
            uint4 v = ((const uint4*)(A + (size_t)gr * 64))[j];
            *(uint4*)(smem + SM_A + row * 272 + j * 16) = v;
        }
        __syncthreads();
        mma_phase(smem, m0, B, O, wid, lane);
        __syncthreads();
    }
}

// ---------------- CSR gather aggregation: 2 nodes/warp, packed bf16x2 tree adds ----------------
// lanes 0-15 -> node 2p, lanes 16-31 -> node 2p+1; each lane = 8 channels (uint4).
// 4-edge groups summed with add.rn.bf16x2 (12 ops), promoted to fp32 once per group.
__global__ __launch_bounds__(256) void k_agg(const uint32_t* __restrict__ M,
                                             uint32_t* __restrict__ A,
                                             const int* __restrict__ batch,
                                             int mode) {
    int pair = blockIdx.x * 8 + (threadIdx.x >> 5);
    int lane = threadIdx.x & 31;
    int half = lane >> 4;
    int hl   = lane & 15;
    int node = pair * 2 + half;
    if (node >= N_NODES) return;
    const uint4* H4 = (const uint4*)M + hl;

    uint4 hn = ldcg_u4(H4 + (size_t)node * 16);
    float a0 = bflo(hn.x), a1 = bfhi(hn.x), a2 = bflo(hn.y), a3 = bfhi(hn.y);
    float a4 = bflo(hn.z), a5 = bfhi(hn.z), a6 = bflo(hn.w), a7 = bfhi(hn.w);

    int e   = g_rowstart[node];
    int end = g_rowstart[node + 1];

    // 4-edge groups: bf16x2 tree (12 packed adds) -> fp32 promote (8 extract + 8 fadd)
    for (; e + 4 <= end; e += 4) {
        int s0 = g_col[e + 0], s1 = g_col[e + 1], s2 = g_col[e + 2], s3 = g_col[e + 3];
        uint4 v0 = ldcg_u4(H4 + (size_t)s0 * 16);
        uint4 v1 = ldcg_u4(H4 + (size_t)s1 * 16);
        uint4 v2 = ldcg_u4(H4 + (size_t)s2 * 16);
        uint4 v3 = ldcg_u4(H4 + (size_t)s3 * 16);
        uint32_t tx = badd2(badd2(v0.x, v1.x), badd2(v2.x, v3.x));
        uint32_t ty = badd2(badd2(v0.y, v1.y), badd2(v2.y, v3.y));
        uint32_t tz = badd2(badd2(v0.z, v1.z), badd2(v2.z, v3.z));
        uint32_t tw = badd2(badd2(v0.w, v1.w), badd2(v2.w, v3.w));
        a0 += bflo(tx); a1 += bfhi(tx);
        a2 += bflo(ty); a3 += bfhi(ty);
        a4 += bflo(tz); a5 += bfhi(tz);
        a6 += bflo(tw); a7 += bfhi(tw);
    }
    for (; e < end; e++) {
        uint4 v = ldcg_u4(H4 + (size_t)g_col[e] * 16);
        a0 += bflo(v.x); a1 += bfhi(v.x);
        a2 += bflo(v.y); a3 += bfhi(v.y);
        a4 += bflo(v.z); a5 += bfhi(v.z);
        a6 += bflo(v.w); a7 += bfhi(v.w);
    }

    float dn = g_dinv[node];
    a0 *= dn; a1 *= dn; a2 *= dn; a3 *= dn;
    a4 *= dn; a5 *= dn; a6 *= dn; a7 *= dn;

    if (mode == 0) {
        a0 = fmaxf(a0, 0.f); a1 = fmaxf(a1, 0.f);
        a2 = fmaxf(a2, 0.f); a3 = fmaxf(a3, 0.f);
        a4 = fmaxf(a4, 0.f); a5 = fmaxf(a5, 0.f);
        a6 = fmaxf(a6, 0.f); a7 = fmaxf(a7, 0.f);
        uint4 o;
        o.x = pack_bf2(a0, a1); o.y = pack_bf2(a2, a3);
        o.z = pack_bf2(a4, a5); o.w = pack_bf2(a6, a7);
        ((uint4*)A)[(size_t)node * 16 + hl] = o;
    } else {
        int g = batch[node];
        float* dst = &g_pool[g * CH + hl * 8];
        asm volatile("red.global.add.v4.f32 [%0], {%1,%2,%3,%4};"
                     :: "l"(dst), "f"(a0), "f"(a1), "f"(a2), "f"(a3) : "memory");
        asm volatile("red.global.add.v4.f32 [%0], {%1,%2,%3,%4};"
                     :: "l"(dst + 4), "f"(a4), "f"(a5), "f"(a6), "f"(a7) : "memory");
        if (hl == 0) atomicAdd(&g_cnt[g], 1.0f);
    }
}

// ---------------- final projection ----------------
__global__ void k_final(const float* __restrict__ Wp, const float* __restrict__ bp,
                        float* __restrict__ out) {
    int g = blockIdx.x;
    int j = threadIdx.x;
    float inv = 1.0f / fmaxf(g_cnt[g], 1.0f);
    float acc = bp[j];
    #pragma unroll 4
    for (int c = 0; c < CH; c++)
        acc += g_pool[g * CH + c] * inv * Wp[c * OUTC + j];
    out[g * OUTC + j] = acc;
}

// ---------------- launch ----------------
extern "C" void kernel_launch(void* const* d_in, const int* in_sizes, int n_in,
                              void* d_out, int out_size) {
    const float* x   = (const float*)d_in[0];
    const int*   ei  = (const int*)d_in[1];
    const int*   bat = (const int*)d_in[2];
    const float* W1 = (const float*)d_in[3];
    const float* b1 = (const float*)d_in[4];
    const float* W2 = (const float*)d_in[5];
    const float* b2 = (const float*)d_in[6];
    const float* W3 = (const float*)d_in[7];
    const float* b3 = (const float*)d_in[8];
    const float* Wp = (const float*)d_in[9];
    const float* bp = (const float*)d_in[10];
    float* out = (float*)d_out;

    void *pm, *pa;
    cudaGetSymbolAddress(&pm, g_msg);
    cudaGetSymbolAddress(&pa, g_act);
    uint32_t* msg = (uint32_t*)pm;
    uint32_t* act = (uint32_t*)pa;

    static cudaStream_t sB = nullptr;
    static cudaEvent_t ev_fork = nullptr, ev_dinv = nullptr, ev_csr = nullptr;
    if (sB == nullptr) {
        cudaFuncSetAttribute(k_gemm1, cudaFuncAttributeMaxDynamicSharedMemorySize, SM_TOTAL);
        cudaFuncSetAttribute(k_gemm, cudaFuncAttributeMaxDynamicSharedMemorySize, SM_TOTAL);
        cudaStreamCreateWithFlags(&sB, cudaStreamNonBlocking);
        cudaEventCreateWithFlags(&ev_fork, cudaEventDisableTiming);
        cudaEventCreateWithFlags(&ev_dinv, cudaEventDisableTiming);
        cudaEventCreateWithFlags(&ev_csr, cudaEventDisableTiming);
    }

    int nb_nodes = (N_NODES + 255) / 256;
    int nb_e4    = (N_EDGES / 4 + 255) / 256;
    int nb_pair8 = (N_NODES / 2 + 7) / 8;
    int nb_scan1 = (N_NODES + 511) / 512;   // 196
    int nb_w3    = (3 * CH * CH + 255) / 256;

    // side stream: CSR build; dinv early
    cudaEventRecord(ev_fork, 0);
    cudaStreamWaitEvent(sB, ev_fork, 0);
    k_zero <<<nb_nodes, 256, 0, sB>>>();
    k_count<<<nb_e4,    256, 0, sB>>>(ei);
    k_dinv <<<nb_nodes, 256, 0, sB>>>();
    cudaEventRecord(ev_dinv, sB);
    k_scan1<<<nb_scan1, 512, 0, sB>>>();
    k_scan2<<<1,        256, 0, sB>>>(nb_scan1);
    k_scan3<<<nb_nodes, 256, 0, sB>>>();
    k_fill <<<nb_e4,    256, 0, sB>>>(ei);
    cudaEventRecord(ev_csr, sB);

    // main stream
    k_wconv3<<<nb_w3, 256>>>(W1, W2, W3);
    cudaStreamWaitEvent(0, ev_dinv, 0);
    k_gemm1<<<GEMM_GRID, 256, SM_TOTAL>>>(x, b1, msg);     // overlaps scan+fill
    cudaStreamWaitEvent(0, ev_csr, 0);

    k_agg<<<nb_pair8, 256>>>(msg, act, bat, 0);
    k_gemm<<<GEMM_GRID, 256, SM_TOTAL>>>(act, 1, b2, msg);
    k_agg<<<nb_pair8, 256>>>(msg, act, bat, 0);
    k_gemm<<<GEMM_GRID, 256, SM_TOTAL>>>(act, 2, b3, msg);
    k_agg<<<nb_pair8, 256>>>(msg, nullptr, bat, 1);        // fused pooling
    k_final<<<NG, OUTC>>>(Wp, bp, out);
}